// round 9
// baseline (speedup 1.0000x reference)
#include <cuda_runtime.h>
#include <cstdint>

#define UNITS 65
#define G4    260          // 4*UNITS
#define BATCH 50
#define SEQ   8192
#define NROWS (BATCH * SEQ)   // 409600

// ---------------- scratch (device globals; no runtime allocation) ----------------
__device__ float g_zpre[(size_t)NROWS * G4];   // x@W + b, precomputed per (b,t)
__device__ float g_h3[(size_t)NROWS * UNITS];  // layer-3 hidden states (ys)

// ---------------- f32x2 helpers (Blackwell packed fp32 FMA) ----------------
__device__ __forceinline__ unsigned long long pack2(float lo, float hi) {
    unsigned long long v;
    asm("mov.b64 %0, {%1, %2};" : "=l"(v) : "f"(lo), "f"(hi));
    return v;
}
__device__ __forceinline__ unsigned long long ffma2(unsigned long long a,
                                                    unsigned long long b,
                                                    unsigned long long c) {
    unsigned long long d;
    asm("fma.rn.f32x2 %0, %1, %2, %3;" : "=l"(d) : "l"(a), "l"(b), "l"(c));
    return d;
}
__device__ __forceinline__ unsigned long long fadd2(unsigned long long a,
                                                    unsigned long long b) {
    unsigned long long d;
    asm("add.rn.f32x2 %0, %1, %2;" : "=l"(d) : "l"(a), "l"(b));
    return d;
}
__device__ __forceinline__ float hsum4(unsigned long long a0, unsigned long long a1) {
    unsigned long long s = fadd2(a0, a1);
    float x0, x1;
    asm("mov.b64 {%0, %1}, %2;" : "=f"(x0), "=f"(x1) : "l"(s));
    return x0 + x1;
}

// dot over K=65 (padded to 66 with zero): sh must be 16B-aligned float[68] with
// sh[65] == 0; col[33] holds weight pairs (col[32].hi == 0).
__device__ __forceinline__ void dot33(const float* __restrict__ sh,
                                      const unsigned long long* col,
                                      unsigned long long& a0,
                                      unsigned long long& a1) {
    const ulonglong2* hp = reinterpret_cast<const ulonglong2*>(sh);
#pragma unroll
    for (int m = 0; m < 16; m++) {
        ulonglong2 p = hp[m];
        a0 = ffma2(p.x, col[2 * m + 0], a0);
        a1 = ffma2(p.y, col[2 * m + 1], a1);
    }
    unsigned long long last = *reinterpret_cast<const unsigned long long*>(sh + 64);
    a0 = ffma2(last, col[32], a0);
}

// 16-lane K-split mini-dot for one output column: lane group of 16 covers
// k = 0..63 (4 each via float4) + k=64 (nonzero w64 on lane idx&15==15 only).
// xor-butterfly leaves the full sum on every lane of the 16-group.
__device__ __forceinline__ float minidot(const float* __restrict__ sh,
                                         float4 wv, float w64, int kb) {
    float4 h = *reinterpret_cast<const float4*>(sh + kb);
    float p = h.x * wv.x;
    p = fmaf(h.y, wv.y, p);
    p = fmaf(h.z, wv.z, p);
    p = fmaf(h.w, wv.w, p);
    p = fmaf(sh[64], w64, p);
    p += __shfl_xor_sync(0xffffffffu, p, 1, 16);
    p += __shfl_xor_sync(0xffffffffu, p, 2, 16);
    p += __shfl_xor_sync(0xffffffffu, p, 4, 16);
    p += __shfl_xor_sync(0xffffffffu, p, 8, 16);
    return p;
}

// ---------------- fast activations (ex2/rcp approx: ~1e-6 rel err) ----------------
__device__ __forceinline__ float fast_ex2(float x) {
    float y; asm("ex2.approx.f32 %0, %1;" : "=f"(y) : "f"(x)); return y;
}
__device__ __forceinline__ float fast_rcp(float x) {
    float y; asm("rcp.approx.f32 %0, %1;" : "=f"(y) : "f"(x)); return y;
}
#define LOG2E 1.4426950408889634f
__device__ __forceinline__ float sigm_f(float x) {
    return fast_rcp(1.0f + fast_ex2(-x * LOG2E));
}
__device__ __forceinline__ float tanh_f(float x) {
    return fmaf(-2.0f, fast_rcp(1.0f + fast_ex2(2.0f * LOG2E * x)), 1.0f);
}

__device__ __forceinline__ float act_lstm(const float* __restrict__ z, int ak,
                                          float& c) {
    float zi = z[ak], zf = z[ak + UNITS];
    float zg = z[ak + 2 * UNITS], zo = z[ak + 3 * UNITS];
    c = sigm_f(zf) * c + sigm_f(zi) * tanh_f(zg);
    return sigm_f(zo) * tanh_f(c);
}

// ---------------- kernel 1: zpre = x @ W + b  (all rows, parallel) ----------------
__global__ void __launch_bounds__(G4) pre_kernel(const float* __restrict__ x,
                                                 const float* __restrict__ W,
                                                 const float* __restrict__ b) {
    const int tid = threadIdx.x;           // 0..259  -> gate column
    const int rsub = tid / UNITS;          // 0..3    (x-row loader role)
    const int jl = tid - rsub * UNITS;     // 0..64

    unsigned long long wcol[33];
#pragma unroll
    for (int m = 0; m < 32; m++)
        wcol[m] = pack2(W[(2 * m) * G4 + tid], W[(2 * m + 1) * G4 + tid]);
    wcol[32] = pack2(W[64 * G4 + tid], 0.0f);
    const float bj = b[tid];

    __shared__ __align__(16) float sh_x[4][68];
    if (tid < 12) sh_x[tid / 3][65 + tid % 3] = 0.0f;   // zero pads once
    __syncthreads();

    for (size_t row0 = (size_t)blockIdx.x * 4; row0 < NROWS;
         row0 += (size_t)gridDim.x * 4) {
        __syncthreads();   // previous iteration's reads complete
        sh_x[rsub][jl] = x[(row0 + rsub) * UNITS + jl];
        __syncthreads();
#pragma unroll
        for (int r = 0; r < 4; r++) {
            unsigned long long a0 = 0ull, a1 = 0ull;
            dot33(sh_x[r], wcol, a0, a1);
            g_zpre[(row0 + r) * G4 + tid] = bj + hsum4(a0, a1);
        }
    }
}

// ---------------- kernel 2: persistent recurrence, one block per batch row ----------
// 352 threads, 11 warps:
//   warps 0-7  (j<256)      : dot threads, outputs 0..255, weights in registers.
//                             EXACTLY 2 dot warps per SMSP (the R5 version had 3 on
//                             SMSP0 -> 402-cyc critical phase; now 268).
//   warps 8-9  (j 256..319) : act threads (unit ak=j-256) AND 16-lane mini-dots
//                             covering outputs 256..259 (4 outputs x 16 lanes).
//   warp 10 lane 0 (j=320)  : act for unit 64 only.
// 5 phases/step; every phase pairs an activation with an independent dot.
// All u-dot partial results live in single float registers (producer==consumer
// thread), zero smem staging, one live f32x2 accumulator pair -> no spills.
__global__ void __launch_bounds__(352, 1) rec_kernel(const float* __restrict__ W,
                                                     const float* __restrict__ U,
                                                     const float* __restrict__ b) {
    const int j = threadIdx.x;
    const int row = blockIdx.x;

    __shared__ __align__(16) float sh_h1[68], sh_h2[68], sh_h3[68];
    __shared__ float sh_z1[G4], sh_z2[G4], sh_z3[G4];

    const bool is_dot = (j < 256);
    const bool is_mini = (j >= 256) && (j < 320);
    const bool is_act = (j >= 256) && (j <= 320);
    const int ak = j - 256;               // act unit 0..64

    // ---- dot-thread state ----
    unsigned long long wcol[33], ucol[33];
    float bj = 0.0f, zp = 0.0f, u1v = 0.0f, u2v = 0.0f, u3v = 0.0f;
    if (is_dot) {
#pragma unroll
        for (int m = 0; m < 32; m++) {
            wcol[m] = pack2(W[(2 * m) * G4 + j], W[(2 * m + 1) * G4 + j]);
            ucol[m] = pack2(U[(2 * m) * G4 + j], U[(2 * m + 1) * G4 + j]);
        }
        wcol[32] = pack2(W[64 * G4 + j], 0.0f);
        ucol[32] = pack2(U[64 * G4 + j], 0.0f);
        bj = b[j];
    }

    // ---- mini-thread state (outputs 256..259) ----
    float4 mwx = {0, 0, 0, 0}, mux = {0, 0, 0, 0};
    float mw64 = 0.f, mu64 = 0.f, mbx = 0.f;
    float zpx = 0.f, u1x = 0.f, u2x = 0.f, u3x = 0.f;
    int mj = 0, mkb = 0;
    bool lead = false;
    if (is_mini) {
        int idx = j - 256;                // 0..63
        int g = idx >> 4;                 // 0..3 -> output 256+g
        mj = 256 + g;
        mkb = (idx & 15) * 4;             // k base 0,4,...,60
        mwx.x = W[(mkb + 0) * G4 + mj];
        mwx.y = W[(mkb + 1) * G4 + mj];
        mwx.z = W[(mkb + 2) * G4 + mj];
        mwx.w = W[(mkb + 3) * G4 + mj];
        mux.x = U[(mkb + 0) * G4 + mj];
        mux.y = U[(mkb + 1) * G4 + mj];
        mux.z = U[(mkb + 2) * G4 + mj];
        mux.w = U[(mkb + 3) * G4 + mj];
        if ((idx & 15) == 15) { mw64 = W[64 * G4 + mj]; mu64 = U[64 * G4 + mj]; }
        mbx = b[mj];
        lead = (idx & 15) == 0;
    }

    // cell states (act threads)
    float c1 = 0.f, c2 = 0.f, c3 = 0.f;

    if (j < 68) { sh_h1[j] = 0.0f; sh_h2[j] = 0.0f; sh_h3[j] = 0.0f; }

    const float* __restrict__ zpre = g_zpre + (size_t)row * SEQ * G4;
    float* __restrict__ h3out = g_h3 + (size_t)row * SEQ * UNITS;

    if (j < G4) sh_z1[j] = zpre[j];   // z1(0) = zpre(0)  (h1(-1)=0); u2v,u3v start 0
    __syncthreads();

    for (int t = 0; t < SEQ; t++) {
        const size_t tn = (size_t)((t + 1 < SEQ) ? t + 1 : t) * G4;

        // ---- P1: u3 = h3(t-1)@U (regs) + prefetch zpre  ||  act1 + mini-u3 ----
        if (is_dot) {
            unsigned long long a0 = 0ull, a1 = 0ull;
            dot33(sh_h3, ucol, a0, a1);
            u3v = hsum4(a0, a1);
            zp = zpre[tn + j];
        } else {
            if (is_mini) {
                u3x = minidot(sh_h3, mux, mu64, mkb);
                if (lead) zpx = zpre[tn + mj];
            }
            if (is_act) sh_h1[ak] = act_lstm(sh_z1, ak, c1);
        }
        __syncthreads();

        // ---- P2: z2 = h1@W + u2 + b ----
        if (is_dot) {
            unsigned long long a0 = 0ull, a1 = 0ull;
            dot33(sh_h1, wcol, a0, a1);
            sh_z2[j] = bj + u2v + hsum4(a0, a1);
        } else if (is_mini) {
            float p = minidot(sh_h1, mwx, mw64, mkb);
            if (lead) sh_z2[mj] = mbx + u2x + p;
        }
        __syncthreads();

        // ---- P3: u1 = h1@U (regs)  ||  act2 + mini-u1 ----
        if (is_dot) {
            unsigned long long a0 = 0ull, a1 = 0ull;
            dot33(sh_h1, ucol, a0, a1);
            u1v = hsum4(a0, a1);
        } else {
            if (is_mini) u1x = minidot(sh_h1, mux, mu64, mkb);
            if (is_act) sh_h2[ak] = act_lstm(sh_z2, ak, c2);
        }
        __syncthreads();

        // ---- P4: z3 = h2@W + u3 + b ----
        if (is_dot) {
            unsigned long long a0 = 0ull, a1 = 0ull;
            dot33(sh_h2, wcol, a0, a1);
            sh_z3[j] = bj + u3v + hsum4(a0, a1);
        } else if (is_mini) {
            float p = minidot(sh_h2, mwx, mw64, mkb);
            if (lead) sh_z3[mj] = mbx + u3x + p;
        }
        __syncthreads();

        // ---- P5: u2 = h2@U (regs), z1(t+1) = zp + u1  ||  act3 + emit + mini-u2 ----
        if (is_dot) {
            unsigned long long a0 = 0ull, a1 = 0ull;
            dot33(sh_h2, ucol, a0, a1);
            u2v = hsum4(a0, a1);
            sh_z1[j] = zp + u1v;
        } else {
            if (is_mini) {
                u2x = minidot(sh_h2, mux, mu64, mkb);
                if (lead) sh_z1[mj] = zpx + u1x;
            }
            if (is_act) {
                float hn = act_lstm(sh_z3, ak, c3);
                sh_h3[ak] = hn;
                h3out[(size_t)t * UNITS + ak] = hn;
            }
        }
        __syncthreads();
    }
}

// ---------------- kernel 3: out = ys @ Wd + bd  (parallel) ----------------
__global__ void __launch_bounds__(G4) dense_kernel(const float* __restrict__ Wd,
                                                   const float* __restrict__ bd,
                                                   float* __restrict__ out) {
    const int tid = threadIdx.x;           // 0..259
    const int rsub = tid / UNITS;          // 0..3
    const int jl = tid - rsub * UNITS;     // 0..64 -> output column

    unsigned long long wdcol[33];
#pragma unroll
    for (int m = 0; m < 32; m++)
        wdcol[m] = pack2(Wd[(2 * m) * UNITS + jl], Wd[(2 * m + 1) * UNITS + jl]);
    wdcol[32] = pack2(Wd[64 * UNITS + jl], 0.0f);
    const float bj = bd[jl];

    __shared__ __align__(16) float sh_y[4][68];
    if (tid < 12) sh_y[tid / 3][65 + tid % 3] = 0.0f;
    __syncthreads();

    for (size_t row0 = (size_t)blockIdx.x * 4; row0 < NROWS;
         row0 += (size_t)gridDim.x * 4) {
        __syncthreads();
        sh_y[rsub][jl] = g_h3[(row0 + rsub) * UNITS + jl];
        __syncthreads();
        unsigned long long a0 = 0ull, a1 = 0ull;
        dot33(sh_y[rsub], wdcol, a0, a1);
        out[(row0 + rsub) * UNITS + jl] = bj + hsum4(a0, a1);
    }
}

// ---------------- launch ----------------
extern "C" void kernel_launch(void* const* d_in, const int* in_sizes, int n_in,
                              void* d_out, int out_size) {
    const float* x  = (const float*)d_in[0];
    const float* W  = (const float*)d_in[1];
    const float* U  = (const float*)d_in[2];
    const float* b  = (const float*)d_in[3];
    const float* Wd = (const float*)d_in[4];
    const float* bd = (const float*)d_in[5];
    float* out = (float*)d_out;

    pre_kernel<<<1184, G4>>>(x, W, b);
    rec_kernel<<<BATCH, 352>>>(W, U, b);
    dense_kernel<<<1184, G4>>>(Wd, bd, out);
}

// round 11
// speedup vs baseline: 1.5670x; 1.5670x over previous
#include <cuda_runtime.h>
#include <cstdint>

#define UNITS 65
#define G4    260          // 4*UNITS
#define BATCH 50
#define SEQ   8192
#define NROWS (BATCH * SEQ)   // 409600

// ---------------- scratch (device globals; no runtime allocation) ----------------
__device__ float g_zpre[(size_t)NROWS * G4];     // x@W + b, precomputed per (b,t)
__device__ float g_h2s[(size_t)NROWS * UNITS];   // layer-2 hidden stream (A -> B)
__device__ float g_h3[(size_t)NROWS * UNITS];    // layer-3 hidden states (ys)
__device__ unsigned int g_flag[BATCH];           // per-row completed-step counter

// ---------------- f32x2 helpers (Blackwell packed fp32 FMA) ----------------
__device__ __forceinline__ unsigned long long pack2(float lo, float hi) {
    unsigned long long v;
    asm("mov.b64 %0, {%1, %2};" : "=l"(v) : "f"(lo), "f"(hi));
    return v;
}
__device__ __forceinline__ unsigned long long ffma2(unsigned long long a,
                                                    unsigned long long b,
                                                    unsigned long long c) {
    unsigned long long d;
    asm("fma.rn.f32x2 %0, %1, %2, %3;" : "=l"(d) : "l"(a), "l"(b), "l"(c));
    return d;
}
__device__ __forceinline__ unsigned long long fadd2(unsigned long long a,
                                                    unsigned long long b) {
    unsigned long long d;
    asm("add.rn.f32x2 %0, %1, %2;" : "=l"(d) : "l"(a), "l"(b));
    return d;
}
__device__ __forceinline__ float hsum4(unsigned long long a0, unsigned long long a1) {
    unsigned long long s = fadd2(a0, a1);
    float x0, x1;
    asm("mov.b64 {%0, %1}, %2;" : "=f"(x0), "=f"(x1) : "l"(s));
    return x0 + x1;
}

// dot over K=65 (padded to 66 with zero): sh must be 16B-aligned float[68] with
// sh[65] == 0; col[33] holds weight pairs (col[32].hi == 0).
__device__ __forceinline__ void dot33(const float* __restrict__ sh,
                                      const unsigned long long* col,
                                      unsigned long long& a0,
                                      unsigned long long& a1) {
    const ulonglong2* hp = reinterpret_cast<const ulonglong2*>(sh);
#pragma unroll
    for (int m = 0; m < 16; m++) {
        ulonglong2 p = hp[m];
        a0 = ffma2(p.x, col[2 * m + 0], a0);
        a1 = ffma2(p.y, col[2 * m + 1], a1);
    }
    unsigned long long last = *reinterpret_cast<const unsigned long long*>(sh + 64);
    a0 = ffma2(last, col[32], a0);
}

// ---------------- acquire/release flag helpers ----------------
__device__ __forceinline__ unsigned int ld_acq(const unsigned int* p) {
    unsigned int v;
    asm volatile("ld.acquire.gpu.u32 %0, [%1];" : "=r"(v) : "l"(p) : "memory");
    return v;
}
__device__ __forceinline__ void st_rel(unsigned int* p, unsigned int v) {
    asm volatile("st.release.gpu.u32 [%0], %1;" :: "l"(p), "r"(v) : "memory");
}

// ---------------- fast activations (ex2/rcp approx: ~1e-6 rel err) ----------------
__device__ __forceinline__ float fast_ex2(float x) {
    float y; asm("ex2.approx.f32 %0, %1;" : "=f"(y) : "f"(x)); return y;
}
__device__ __forceinline__ float fast_rcp(float x) {
    float y; asm("rcp.approx.f32 %0, %1;" : "=f"(y) : "f"(x)); return y;
}
#define LOG2E 1.4426950408889634f
__device__ __forceinline__ float sigm_f(float x) {
    return fast_rcp(1.0f + fast_ex2(-x * LOG2E));
}
__device__ __forceinline__ float tanh_f(float x) {
    return fmaf(-2.0f, fast_rcp(1.0f + fast_ex2(2.0f * LOG2E * x)), 1.0f);
}
__device__ __forceinline__ float act_lstm(const float* __restrict__ z, int ak,
                                          float& c) {
    float zi = z[ak], zf = z[ak + UNITS];
    float zg = z[ak + 2 * UNITS], zo = z[ak + 3 * UNITS];
    c = sigm_f(zf) * c + sigm_f(zi) * tanh_f(zg);
    return sigm_f(zo) * tanh_f(c);
}

// ---------------- kernel 0: reset flags (every launch / graph replay) ------------
__global__ void init_kernel() {
    if (threadIdx.x < BATCH) g_flag[threadIdx.x] = 0;
}

// ---------------- kernel 1: zpre = x @ W + b  (all rows, parallel) ----------------
__global__ void __launch_bounds__(G4) pre_kernel(const float* __restrict__ x,
                                                 const float* __restrict__ W,
                                                 const float* __restrict__ b) {
    const int tid = threadIdx.x;           // 0..259  -> gate column
    const int rsub = tid / UNITS;          // 0..3    (x-row loader role)
    const int jl = tid - rsub * UNITS;     // 0..64

    unsigned long long wcol[33];
#pragma unroll
    for (int m = 0; m < 32; m++)
        wcol[m] = pack2(W[(2 * m) * G4 + tid], W[(2 * m + 1) * G4 + tid]);
    wcol[32] = pack2(W[64 * G4 + tid], 0.0f);
    const float bj = b[tid];

    __shared__ __align__(16) float sh_x[4][68];
    if (tid < 12) sh_x[tid / 3][65 + tid % 3] = 0.0f;   // zero pads once
    __syncthreads();

    for (size_t row0 = (size_t)blockIdx.x * 4; row0 < NROWS;
         row0 += (size_t)gridDim.x * 4) {
        __syncthreads();   // previous iteration's reads complete
        sh_x[rsub][jl] = x[(row0 + rsub) * UNITS + jl];
        __syncthreads();
#pragma unroll
        for (int r = 0; r < 4; r++) {
            unsigned long long a0 = 0ull, a1 = 0ull;
            dot33(sh_x[r], wcol, a0, a1);
            g_zpre[(row0 + r) * G4 + tid] = bj + hsum4(a0, a1);
        }
    }
}

// ---------------- kernel 2: layer-wavefront recurrence, 2 SMs per batch row ------
// Grid = 100 blocks (single wave on 148 SMs -> all resident), 320 threads:
//   bid <  50 : "A" block, row = bid        -> layers 1 + 2 (3 phases/step)
//   bid >= 50 : "B" block, row = bid - 50   -> layer 3      (2 phases/step)
// A streams h2(t) to g_h2s; thread j=319 (warp 9, idle in A's compute) publishes
// progress in g_flag[row] every 4 steps via syncthreads -> threadfence ->
// st.release (fence cost fully off the dot warps). B's warp 9 spins with
// ld.acquire and double-buffers h2 one step ahead. A never waits on B and always
// publishes flag=SEQ at the end -> every B spin terminates; no deadlock.
__global__ void __launch_bounds__(320, 1) rec2_kernel(const float* __restrict__ W,
                                                      const float* __restrict__ U,
                                                      const float* __restrict__ b) {
    const int j = threadIdx.x;
    const bool isA = (blockIdx.x < BATCH);
    const int row = isA ? blockIdx.x : (blockIdx.x - BATCH);

    __shared__ __align__(16) float sh_ha[68], sh_hb[68];   // A: h1,h2 / B: h3,(unused)
    __shared__ __align__(16) float sh_buf[2][68];          // B: h2 double buffer
    __shared__ float sh_za[G4], sh_zb[G4];                 // A: z1,z2 / B: z3,(unused)

    // ---- weights in registers on dot threads (j < 260) ----
    unsigned long long wcol[33], ucol[33];
    float bj = 0.0f;
    if (j < G4) {
#pragma unroll
        for (int m = 0; m < 32; m++) {
            wcol[m] = pack2(W[(2 * m) * G4 + j], W[(2 * m + 1) * G4 + j]);
            ucol[m] = pack2(U[(2 * m) * G4 + j], U[(2 * m + 1) * G4 + j]);
        }
        wcol[32] = pack2(W[64 * G4 + j], 0.0f);
        ucol[32] = pack2(U[64 * G4 + j], 0.0f);
        bj = b[j];
    }
    if (j < 68) {
        sh_ha[j] = 0.0f; sh_hb[j] = 0.0f;
        sh_buf[0][j] = 0.0f; sh_buf[1][j] = 0.0f;
    }

    if (isA) {
        // ================= A: layers 1 + 2 =================
        const float* __restrict__ zpre = g_zpre + (size_t)row * SEQ * G4;
        float* __restrict__ h2out = g_h2s + (size_t)row * SEQ * UNITS;
        unsigned int* flag = &g_flag[row];
        const bool is_pub = (j == 319);    // warp 9: publication duty only

        float c1 = 0.f, c2 = 0.f;
        float zp = 0.f, u1v = 0.f, u2v = 0.f;

        if (j < G4) sh_za[j] = zpre[j];    // z1(0) = zpre(0)  (h1(-1)=0)
        __syncthreads();

        for (int t = 0; t < SEQ; t++) {
            const size_t tn = (size_t)((t + 1 < SEQ) ? t + 1 : t) * G4;

            // P1: u2 = h2(t-1)@U + zpre prefetch  ||  act1(z1)->h1  ||  flag pub
            if (j < G4) {
                unsigned long long a0 = 0ull, a1 = 0ull;
                dot33(sh_hb, ucol, a0, a1);
                u2v = hsum4(a0, a1);
                zp = zpre[tn + j];
            } else if (is_pub && t > 0 && (t & 3) == 0) {
                __threadfence();           // h2 STGs (< t) visible (post-barrier)
                st_rel(flag, (unsigned)t); // t steps fully completed
            }
            if (j < UNITS) sh_ha[j] = act_lstm(sh_za, j, c1);
            __syncthreads();

            // P2: z2 = h1@W + u2 + b
            if (j < G4) {
                unsigned long long a0 = 0ull, a1 = 0ull;
                dot33(sh_ha, wcol, a0, a1);
                sh_zb[j] = bj + u2v + hsum4(a0, a1);
            }
            __syncthreads();

            // P3: u1 = h1@U, z1(t+1) = zp + u1  ||  act2(z2)->h2 + STG h2
            if (j < G4) {
                unsigned long long a0 = 0ull, a1 = 0ull;
                dot33(sh_ha, ucol, a0, a1);
                u1v = hsum4(a0, a1);
                sh_za[j] = zp + u1v;
            }
            if (j < UNITS) {
                float hn = act_lstm(sh_zb, j, c2);
                sh_hb[j] = hn;
                h2out[(size_t)t * UNITS + j] = hn;
            }
            __syncthreads();
        }
        if (is_pub) {                      // final publication (B depends on it)
            __threadfence();
            st_rel(flag, (unsigned)SEQ);
        }
    } else {
        // ================= B: layer 3 =================
        const float* __restrict__ h2in = g_h2s + (size_t)row * SEQ * UNITS;
        float* __restrict__ h3out = g_h3 + (size_t)row * SEQ * UNITS;
        const unsigned int* flag = &g_flag[row];
        const int lane = j - 288;          // warp 9 = fetch warp
        float c3 = 0.f;

        // initial fetch: h2(0) -> buf[0]
        if (lane >= 0) {
            while (ld_acq(flag) < 1u) __nanosleep(64);
            for (int u = lane; u < UNITS; u += 32)
                sh_buf[0][u] = h2in[u];
        }
        __syncthreads();

        for (int t = 0; t < SEQ; t++) {
            // P1: z3 = h2(t)@W + h3(t-1)@U + b  ||  warp9: fetch h2(t+1)
            if (j < G4) {
                unsigned long long a0 = 0ull, a1 = 0ull;
                dot33(sh_buf[t & 1], wcol, a0, a1);
                dot33(sh_ha, ucol, a0, a1);            // sh_ha = h3
                sh_za[j] = bj + hsum4(a0, a1);
            } else if (lane >= 0) {
                int tsrc = (t + 1 < SEQ) ? t + 1 : SEQ - 1;
                while (ld_acq(flag) < (unsigned)(tsrc + 1)) __nanosleep(64);
                for (int u = lane; u < UNITS; u += 32)
                    sh_buf[(t + 1) & 1][u] = h2in[(size_t)tsrc * UNITS + u];
            }
            __syncthreads();

            // P2: act3(z3) -> h3, emit
            if (j < UNITS) {
                float hn = act_lstm(sh_za, j, c3);
                sh_ha[j] = hn;
                h3out[(size_t)t * UNITS + j] = hn;
            }
            __syncthreads();
        }
    }
}

// ---------------- kernel 3: out = ys @ Wd + bd  (parallel) ----------------
__global__ void __launch_bounds__(G4) dense_kernel(const float* __restrict__ Wd,
                                                   const float* __restrict__ bd,
                                                   float* __restrict__ out) {
    const int tid = threadIdx.x;           // 0..259
    const int rsub = tid / UNITS;          // 0..3
    const int jl = tid - rsub * UNITS;     // 0..64 -> output column

    unsigned long long wdcol[33];
#pragma unroll
    for (int m = 0; m < 32; m++)
        wdcol[m] = pack2(Wd[(2 * m) * UNITS + jl], Wd[(2 * m + 1) * UNITS + jl]);
    wdcol[32] = pack2(Wd[64 * UNITS + jl], 0.0f);
    const float bj = bd[jl];

    __shared__ __align__(16) float sh_y[4][68];
    if (tid < 12) sh_y[tid / 3][65 + tid % 3] = 0.0f;
    __syncthreads();

    for (size_t row0 = (size_t)blockIdx.x * 4; row0 < NROWS;
         row0 += (size_t)gridDim.x * 4) {
        __syncthreads();
        sh_y[rsub][jl] = g_h3[(row0 + rsub) * UNITS + jl];
        __syncthreads();
        unsigned long long a0 = 0ull, a1 = 0ull;
        dot33(sh_y[rsub], wdcol, a0, a1);
        out[(row0 + rsub) * UNITS + jl] = bj + hsum4(a0, a1);
    }
}

// ---------------- launch ----------------
extern "C" void kernel_launch(void* const* d_in, const int* in_sizes, int n_in,
                              void* d_out, int out_size) {
    const float* x  = (const float*)d_in[0];
    const float* W  = (const float*)d_in[1];
    const float* U  = (const float*)d_in[2];
    const float* b  = (const float*)d_in[3];
    const float* Wd = (const float*)d_in[4];
    const float* bd = (const float*)d_in[5];
    float* out = (float*)d_out;

    init_kernel<<<1, 64>>>();
    pre_kernel<<<1184, G4>>>(x, W, b);
    rec2_kernel<<<2 * BATCH, 320>>>(W, U, b);
    dense_kernel<<<1184, G4>>>(Wd, bd, out);
}